// round 11
// baseline (speedup 1.0000x reference)
#include <cuda_runtime.h>

#define NN 100000
#define EMAX 2000000
#define NBLK 391                             /* ceil(NN/256) */
#define EPSV 1.4142135623730951f
#define ONE_PE 2.4142135623730951f          /* 1 + sqrt(2) */
#define INV_SQRT128 0.08838834764831845f    /* 1/sqrt(128) */

typedef unsigned long long ull;

// ---------------- scratch (device globals: allocation-free) ----------------
__device__ int   g_is32;
__device__ float g_inv[NN];
__device__ int   g_cnt_t[NN];
__device__ int   g_cnt_s[NN];
__device__ int   g_fill[NN];
__device__ int   g_rowptr[NN + 1];
__device__ int   g_bsum[512];
__device__ int   g_perm[EMAX];
__device__ float g_wt[540672];               /* transposed weights */
__device__ float g_bufA[(size_t)NN * 128];
__device__ float g_bufB[(size_t)NN * 128];
__device__ float g_bufC[(size_t)NN * 128];
__device__ float g_z1[(size_t)NN * 512];
__device__ float g_z2[(size_t)NN * 512];

// transposed-weight offsets (floats)
#define OFF_MPW0T 0
#define OFF_MPW1T 16384
#define OFF_MPW2T 32768
#define OFF_FCW0T 49152
#define OFF_PW0T  114688
#define OFF_FCW1T 180224
#define OFF_PW1T  442368
#define OFF_OUTWT 507904

__device__ __forceinline__ float* dbuf(int id) {
    switch (id) {
        case 0: return g_bufA;
        case 1: return g_bufB;
        case 2: return g_bufC;
        case 3: return g_z1;
        case 4: return g_z2;
        default: return nullptr;
    }
}

// ---------------- packed fp32x2 helpers (Blackwell FFMA2 path) -------------
__device__ __forceinline__ void ffma2(ull &d, ull a, ull b) {
    asm("fma.rn.f32x2 %0, %1, %2, %0;" : "+l"(d) : "l"(a), "l"(b));
}
__device__ __forceinline__ float2 unpack2(ull v) {
    float x, y;
    asm("mov.b64 {%0, %1}, %2;" : "=f"(x), "=f"(y) : "l"(v));
    return make_float2(x, y);
}

// ---------------- edge dtype detection (parallel, no serial break) ---------
__global__ void detect_kernel(const void* __restrict__ ei) {
    const ull* p = (const ull*)ei;
    int bad = 0;
    for (int i = threadIdx.x; i < 4096; i += 256)
        if (p[i] > 0xFFFFFFFFull) bad = 1;
    bad = __syncthreads_or(bad);
    if (threadIdx.x == 0) g_is32 = bad;
}

__device__ __forceinline__ void load_edge(const void* ei, int E, int e,
                                          int is32, int& t, int& s) {
    if (is32) {
        const int* p = (const int*)ei;
        t = p[e]; s = p[E + e];
    } else {
        const long long* p = (const long long*)ei;
        t = (int)p[e]; s = (int)p[E + e];
    }
}

// ---------------- weight transpose: Wt[n*K+k] = W[k*N+n] -------------------
__global__ void transpose_kernel(const float* __restrict__ W, int K, int N,
                                 int dstOff) {
    int idx = blockIdx.x * blockDim.x + threadIdx.x;
    if (idx >= K * N) return;
    int n = idx % N, k = idx / N;
    g_wt[dstOff + n * K + k] = W[k * N + n];
}

// ---------------- graph preprocessing --------------------------------------
__global__ void zero_kernel() {
    int i = blockIdx.x * blockDim.x + threadIdx.x;
    if (i < NN) { g_cnt_t[i] = 0; g_cnt_s[i] = 0; g_fill[i] = 0; }
}

__global__ void hist_kernel(const void* __restrict__ ei, int E) {
    int e = blockIdx.x * blockDim.x + threadIdx.x;
    if (e >= E) return;
    int t, s;
    load_edge(ei, E, e, g_is32, t, s);
    if ((unsigned)t < NN) atomicAdd(&g_cnt_t[t], 1);
    if ((unsigned)s < NN) atomicAdd(&g_cnt_s[s], 1);
}

// parallel scan phase 1: per-block sums of cnt_t, plus inv-norm
__global__ void pre1_kernel() {
    __shared__ int sh[256];
    int b = blockIdx.x, t = threadIdx.x;
    int i = b * 256 + t;
    int c = 0;
    if (i < NN) {
        c = g_cnt_t[i];
        g_inv[i] = INV_SQRT128 / (1.0f + EPSV + (float)g_cnt_s[i]);
    }
    sh[t] = c;
    __syncthreads();
    for (int off = 128; off > 0; off >>= 1) {
        if (t < off) sh[t] += sh[t + off];
        __syncthreads();
    }
    if (t == 0) g_bsum[b] = sh[0];
}

// phase 2: exclusive scan of NBLK block sums (single block)
__global__ void pre2_kernel(int E) {
    __shared__ int sh[512];
    int t = threadIdx.x;
    int v = (t < NBLK) ? g_bsum[t] : 0;
    sh[t] = v;
    __syncthreads();
    for (int off = 1; off < 512; off <<= 1) {
        int u = (t >= off) ? sh[t - off] : 0;
        __syncthreads();
        sh[t] += u;
        __syncthreads();
    }
    if (t < NBLK) g_bsum[t] = sh[t] - v;   // exclusive
    if (t == 0) g_rowptr[NN] = E;
}

// phase 3: per-block exclusive prefix + base -> rowptr
__global__ void pre3_kernel() {
    __shared__ int sh[256];
    int b = blockIdx.x, t = threadIdx.x;
    int i = b * 256 + t;
    int v = (i < NN) ? g_cnt_t[i] : 0;
    sh[t] = v;
    __syncthreads();
    for (int off = 1; off < 256; off <<= 1) {
        int u = (t >= off) ? sh[t - off] : 0;
        __syncthreads();
        sh[t] += u;
        __syncthreads();
    }
    if (i < NN) g_rowptr[i] = g_bsum[b] + sh[t] - v;
}

__global__ void fill_kernel(const void* __restrict__ ei, int E) {
    int e = blockIdx.x * blockDim.x + threadIdx.x;
    if (e >= E) return;
    int t, s;
    load_edge(ei, E, e, g_is32, t, s);
    if ((unsigned)t < NN && (unsigned)s < NN) {
        int p = atomicAdd(&g_fill[t], 1);
        int pos = g_rowptr[t] + p;
        if ((unsigned)pos < EMAX) g_perm[pos] = s;
    }
}

// ---------------- GEMM v2: C = act(A1)@W1 [+ A2@W2] + epilogue -------------
// BM=128, BK=16, 256 threads. Thread (tx=tid&15, ty=tid>>4) computes an
// 8-row x TN-col tile: rows ty*8..+7 (as 4 row-pairs), cols tx*TN..+TN-1.
// SMEM: A stored as row-pair-interleaved float2 (LDS.64 -> packed acc operand)
//       W stored transposed + duplicated float2 (LDS.64 -> broadcast operand)
// Inner loop: 12 LDS.64 + 32 FFMA2 per k, zero packing movs.
template <int BN, int TN>
__global__ __launch_bounds__(256, 2)
void gemm_kernel(const float* __restrict__ A1ext, int a1_id, int K1, int reluA1,
                 int a2_id, int K2,
                 int w1_off, int w2_off,
                 const float* __restrict__ b1, const float* __restrict__ b2,
                 float* __restrict__ OutExt, int out_id,
                 int M, int N, int mode)   // mode 0: relu(.+b)*inv; 1: .+b1(+b2)
{
    constexpr int BM = 128, BK = 16;
    constexpr int SROW = 2 * BK + 2;       // 34 floats: pad for bank spread
    __shared__ float As2[BM / 2][SROW];    // [row-pair][2k + parity]
    __shared__ float Wd[BN][SROW];         // [wrow][2k] dup pairs

    const float* A1 = (a1_id < 0) ? A1ext : dbuf(a1_id);
    const float* A2 = dbuf(a2_id);
    float* Out = (out_id < 0) ? OutExt : dbuf(out_id);

    const int tid = threadIdx.x;
    const int tx = tid & 15;
    const int ty = tid >> 4;
    const int bm = blockIdx.x * BM;
    const int bn = blockIdx.y * BN;

    ull acc[4][TN];
#pragma unroll
    for (int r = 0; r < 4; r++)
#pragma unroll
        for (int j = 0; j < TN; j++) acc[r][j] = 0ull;

    for (int pass = 0; pass < 2; ++pass) {
        const float* A = pass ? A2 : A1;
        const int K = pass ? K2 : K1;
        const int woff = pass ? w2_off : w1_off;
        const int doRelu = pass ? 0 : reluA1;
        if (K == 0) continue;
        for (int k0 = 0; k0 < K; k0 += BK) {
            // ---- A tile: BM x BK floats = 512 float4, 2 per thread ----
#pragma unroll
            for (int it = 0; it < 2; ++it) {
                int i = tid + it * 256;
                int row = i >> 2, c4 = i & 3;
                int gr = bm + row;
                float4 v = make_float4(0.f, 0.f, 0.f, 0.f);
                if (gr < M)
                    v = reinterpret_cast<const float4*>(A + (size_t)gr * K + k0)[c4];
                if (doRelu) {
                    v.x = fmaxf(v.x, 0.f); v.y = fmaxf(v.y, 0.f);
                    v.z = fmaxf(v.z, 0.f); v.w = fmaxf(v.w, 0.f);
                }
                int rp = row >> 1, par = row & 1;
                float* dst = &As2[rp][par];
                dst[2 * (4 * c4 + 0)] = v.x;
                dst[2 * (4 * c4 + 1)] = v.y;
                dst[2 * (4 * c4 + 2)] = v.z;
                dst[2 * (4 * c4 + 3)] = v.w;
            }
            // ---- W tile: BN x BK from transposed g_wt, dup-stored ----
            constexpr int WCH = BN * (BK / 4) / 256;   // BN=128 -> 2, BN=64 -> 1
#pragma unroll
            for (int it = 0; it < WCH; ++it) {
                int i = tid + it * 256;
                int col = i % BN, kq = i / BN;
                float4 v = reinterpret_cast<const float4*>(
                               g_wt + woff + (size_t)(bn + col) * K + k0)[kq];
                int wr = (col % TN) * 16 + col / TN;
                float2* dst = reinterpret_cast<float2*>(&Wd[wr][8 * kq]);
                dst[0] = make_float2(v.x, v.x);
                dst[1] = make_float2(v.y, v.y);
                dst[2] = make_float2(v.z, v.z);
                dst[3] = make_float2(v.w, v.w);
            }
            __syncthreads();
            // ---- inner: 12 LDS.64 + 32 FFMA2 per k ----
#pragma unroll
            for (int k = 0; k < BK; k++) {
                ull wv[TN];
#pragma unroll
                for (int j = 0; j < TN; j++)
                    wv[j] = *reinterpret_cast<const ull*>(&Wd[j * 16 + tx][2 * k]);
                ull av[4];
#pragma unroll
                for (int r = 0; r < 4; r++)
                    av[r] = *reinterpret_cast<const ull*>(&As2[ty * 4 + r][2 * k]);
#pragma unroll
                for (int r = 0; r < 4; r++)
#pragma unroll
                    for (int j = 0; j < TN; j++) ffma2(acc[r][j], av[r], wv[j]);
            }
            __syncthreads();
        }
    }

    // ---- epilogue: rows bm+ty*8+2r(+1), cols bn+tx*TN+j ----
    const int ncol0 = bn + tx * TN;
#pragma unroll
    for (int r = 0; r < 4; r++) {
        int m0 = bm + ty * 8 + 2 * r;
        float o0[TN], o1[TN];
#pragma unroll
        for (int j = 0; j < TN; j++) {
            float2 v = unpack2(acc[r][j]);
            float bb = b1[ncol0 + j] + ((mode == 1 && b2) ? b2[ncol0 + j] : 0.f);
            if (mode == 0) {
                o0[j] = fmaxf(v.x + bb, 0.f);
                o1[j] = fmaxf(v.y + bb, 0.f);
            } else {
                o0[j] = v.x + bb;
                o1[j] = v.y + bb;
            }
        }
        if (m0 < M) {
            float s = (mode == 0) ? g_inv[m0] : 1.f;
            float* dst = Out + (size_t)m0 * N + ncol0;
#pragma unroll
            for (int j4 = 0; j4 < TN; j4 += 4)
                *reinterpret_cast<float4*>(dst + j4) =
                    make_float4(o0[j4] * s, o0[j4 + 1] * s, o0[j4 + 2] * s, o0[j4 + 3] * s);
        }
        if (m0 + 1 < M) {
            float s = (mode == 0) ? g_inv[m0 + 1] : 1.f;
            float* dst = Out + (size_t)(m0 + 1) * N + ncol0;
#pragma unroll
            for (int j4 = 0; j4 < TN; j4 += 4)
                *reinterpret_cast<float4*>(dst + j4) =
                    make_float4(o1[j4] * s, o1[j4 + 1] * s, o1[j4 + 2] * s, o1[j4 + 3] * s);
        }
    }
}

// ---------------- aggregation: O[t] = (1+eps)*T[t] + sum_{s in adj(t)} T[s] -
__global__ void aggregate_kernel(int t_id, int o_id) {
    int w = (blockIdx.x * blockDim.x + threadIdx.x) >> 5;
    int lane = threadIdx.x & 31;
    if (w >= NN) return;
    const float4* Tv = reinterpret_cast<const float4*>(dbuf(t_id));
    float4* Ov = reinterpret_cast<float4*>(dbuf(o_id));
    float4 a = Tv[(size_t)w * 32 + lane];
    a.x *= ONE_PE; a.y *= ONE_PE; a.z *= ONE_PE; a.w *= ONE_PE;
    int beg = g_rowptr[w], end = g_rowptr[w + 1];
    int j = beg;
    for (; j + 4 <= end; j += 4) {
        int s0 = g_perm[j + 0];
        int s1 = g_perm[j + 1];
        int s2 = g_perm[j + 2];
        int s3 = g_perm[j + 3];
        float4 v0 = Tv[(size_t)s0 * 32 + lane];
        float4 v1 = Tv[(size_t)s1 * 32 + lane];
        float4 v2 = Tv[(size_t)s2 * 32 + lane];
        float4 v3 = Tv[(size_t)s3 * 32 + lane];
        a.x += v0.x; a.y += v0.y; a.z += v0.z; a.w += v0.w;
        a.x += v1.x; a.y += v1.y; a.z += v1.z; a.w += v1.w;
        a.x += v2.x; a.y += v2.y; a.z += v2.z; a.w += v2.w;
        a.x += v3.x; a.y += v3.y; a.z += v3.z; a.w += v3.w;
    }
    for (; j < end; j++) {
        int s = g_perm[j];
        float4 v = Tv[(size_t)s * 32 + lane];
        a.x += v.x; a.y += v.y; a.z += v.z; a.w += v.w;
    }
    Ov[(size_t)w * 32 + lane] = a;
}

// ---------------- launch ----------------------------------------------------
extern "C" void kernel_launch(void* const* d_in, const int* in_sizes, int n_in,
                              void* d_out, int out_size) {
    const float* x = (const float*)d_in[0];
    const void* ei = d_in[1];
    const int E = in_sizes[1] / 2;
    const float* mpW0 = (const float*)d_in[2];
    const float* mpb0 = (const float*)d_in[3];
    const float* mpW1 = (const float*)d_in[4];
    const float* mpb1 = (const float*)d_in[5];
    const float* mpW2 = (const float*)d_in[6];
    const float* mpb2 = (const float*)d_in[7];
    const float* fcW0 = (const float*)d_in[8];
    const float* fcb0 = (const float*)d_in[9];
    const float* fcW1 = (const float*)d_in[10];
    const float* fcb1 = (const float*)d_in[11];
    const float* pW0  = (const float*)d_in[12];
    const float* pb0  = (const float*)d_in[13];
    const float* pW1  = (const float*)d_in[14];
    const float* pb1  = (const float*)d_in[15];
    const float* outW = (const float*)d_in[16];
    const float* outb = (const float*)d_in[17];
    float* out = (float*)d_out;
    const int M = in_sizes[0] / 128;   // 100000

    // weight transposes (once per replay; tiny)
    transpose_kernel<<<64, 256>>>(mpW0, 128, 128, OFF_MPW0T);
    transpose_kernel<<<64, 256>>>(mpW1, 128, 128, OFF_MPW1T);
    transpose_kernel<<<64, 256>>>(mpW2, 128, 128, OFF_MPW2T);
    transpose_kernel<<<256, 256>>>(fcW0, 128, 512, OFF_FCW0T);
    transpose_kernel<<<256, 256>>>(pW0, 128, 512, OFF_PW0T);
    transpose_kernel<<<1024, 256>>>(fcW1, 512, 512, OFF_FCW1T);
    transpose_kernel<<<256, 256>>>(pW1, 128, 512, OFF_PW1T);
    transpose_kernel<<<128, 256>>>(outW, 512, 64, OFF_OUTWT);

    // graph preprocessing (CSR by target + source-degree norm)
    detect_kernel<<<1, 256>>>(ei);
    zero_kernel<<<NBLK, 256>>>();
    hist_kernel<<<(E + 255) / 256, 256>>>(ei, E);
    pre1_kernel<<<NBLK, 256>>>();
    pre2_kernel<<<1, 512>>>(E);
    pre3_kernel<<<NBLK, 256>>>();
    fill_kernel<<<(E + 255) / 256, 256>>>(ei, E);

    dim3 g128((M + 127) / 128, 1);
    dim3 g512((M + 127) / 128, 4);
    dim3 g64((M + 127) / 128, 1);
    int aggBlocks = (M * 32 + 255) / 256;

    // MP layer 1: x -> bufA (scaled h), aggregate -> bufB
    gemm_kernel<128, 8><<<g128, 256>>>(x, -1, 128, 0, -1, 0,
                                       OFF_MPW0T, 0, mpb0, nullptr,
                                       nullptr, 0, M, 128, 0);
    aggregate_kernel<<<aggBlocks, 256>>>(0, 1);
    // MP layer 2: bufB -> bufA, aggregate -> bufC
    gemm_kernel<128, 8><<<g128, 256>>>(nullptr, 1, 128, 0, -1, 0,
                                       OFF_MPW1T, 0, mpb1, nullptr,
                                       nullptr, 0, M, 128, 0);
    aggregate_kernel<<<aggBlocks, 256>>>(0, 2);
    // MP layer 3: bufC -> bufA, aggregate -> bufB   (bufB = final h, h >= 0)
    gemm_kernel<128, 8><<<g128, 256>>>(nullptr, 2, 128, 0, -1, 0,
                                       OFF_MPW2T, 0, mpb2, nullptr,
                                       nullptr, 0, M, 128, 0);
    aggregate_kernel<<<aggBlocks, 256>>>(0, 1);

    // z1 = relu(h)@fcW0 + h@pW0 + fcb0 + pb0      (h >= 0 so relu(h) == h)
    gemm_kernel<128, 8><<<g512, 256>>>(nullptr, 1, 128, 0, 1, 128,
                                       OFF_FCW0T, OFF_PW0T, fcb0, pb0,
                                       nullptr, 3, M, 512, 1);
    // z2 = relu(z1)@fcW1 + h@pW1 + fcb1 + pb1
    gemm_kernel<128, 8><<<g512, 256>>>(nullptr, 3, 512, 1, 1, 128,
                                       OFF_FCW1T, OFF_PW1T, fcb1, pb1,
                                       nullptr, 4, M, 512, 1);
    // out = z2@outW + outb
    gemm_kernel<64, 4><<<g64, 256>>>(nullptr, 4, 512, 0, -1, 0,
                                     OFF_OUTWT, 0, outb, nullptr,
                                     out, -1, M, 64, 1);
}